// round 5
// baseline (speedup 1.0000x reference)
#include <cuda_runtime.h>
#include <cuda_fp16.h>
#include <cuda.h>
#include <cstdint>

// ---------------- problem constants ----------------
#define B_    16
#define T_    128
#define H_    512
#define L_    2
#define V_    32000
#define M_    (B_ * T_)        // 2048
#define G4_   (4 * H_)         // 2048

// ---------------- GEMM tiling ----------------
#define BM_   128
#define BN_   256
#define BK_   64               // fp16 = 128 bytes/row = SW128 atom
#define KT_   (H_ / BK_)       // 8 k-tiles
#define NSTG  3
#define ST_A  (BM_ * BK_ * 2)  // 16384
#define ST_B  (BN_ * BK_ * 2)  // 32768
#define ST_BYTES (ST_A + ST_B) // 49152
#define SM0   1024
#define SMEM_TOTAL (SM0 + NSTG * ST_BYTES)   // 148480
#define NTHR  512              // 16 warps: 4 m-warps x 4 n-warps, warp tile 32x64

// ---------------- scratch (static device globals) ----------------
__device__ __align__(128) __half g_Ahf[(size_t)M_ * H_];
__device__ __align__(128) __half g_Whf[(size_t)V_ * H_];
__device__ float g_G [(size_t)M_ * G4_];
__device__ float g_hb[B_ * G4_];
__device__ float g_dummy[2 * L_ * B_ * H_];

__device__ __forceinline__ float sigf(float x) { return 1.0f / (1.0f + expf(-x)); }

// ---------------- PTX helpers (base ISA only; no tcgen05 on sm_103 target) ----
__device__ __forceinline__ uint32_t smem_u32(const void* p) {
    uint32_t a;
    asm("{ .reg .u64 t; cvta.to.shared.u64 t, %1; cvt.u32.u64 %0, t; }" : "=r"(a) : "l"(p));
    return a;
}
__device__ __forceinline__ void mbar_init(uint32_t a, uint32_t c) {
    asm volatile("mbarrier.init.shared.b64 [%0], %1;" :: "r"(a), "r"(c) : "memory");
}
__device__ __forceinline__ void mbar_expect_tx(uint32_t a, uint32_t b) {
    asm volatile("mbarrier.arrive.expect_tx.shared.b64 _, [%0], %1;" :: "r"(a), "r"(b) : "memory");
}
__device__ __forceinline__ void mbar_wait(uint32_t a, uint32_t ph) {
    asm volatile(
        "{ .reg .pred P;\n"
        "WL_%=: mbarrier.try_wait.parity.acquire.cta.shared::cta.b64 P, [%0], %1, 0x989680;\n"
        "@P bra.uni WD_%=;\n"
        "bra.uni WL_%=;\n"
        "WD_%=: }" :: "r"(a), "r"(ph) : "memory");
}
__device__ __forceinline__ void tma2d(uint32_t dst, const CUtensorMap* m, int x, int y, uint32_t mbar) {
    asm volatile(
        "cp.async.bulk.tensor.2d.shared::cta.global.tile.mbarrier::complete_tx::bytes "
        "[%0], [%1, {%2, %3}], [%4];"
        :: "r"(dst), "l"(m), "r"(x), "r"(y), "r"(mbar) : "memory");
}
__device__ __forceinline__ void ldsm4(uint32_t& r0, uint32_t& r1, uint32_t& r2, uint32_t& r3,
                                      uint32_t addr) {
    asm volatile("ldmatrix.sync.aligned.m8n8.x4.shared.b16 {%0,%1,%2,%3}, [%4];"
                 : "=r"(r0), "=r"(r1), "=r"(r2), "=r"(r3) : "r"(addr));
}
__device__ __forceinline__ void mma16816(float* c, const uint32_t* a, uint32_t b0, uint32_t b1) {
    asm volatile(
        "mma.sync.aligned.m16n8k16.row.col.f32.f16.f16.f32 "
        "{%0,%1,%2,%3}, {%4,%5,%6,%7}, {%8,%9}, {%0,%1,%2,%3};"
        : "+f"(c[0]), "+f"(c[1]), "+f"(c[2]), "+f"(c[3])
        : "r"(a[0]), "r"(a[1]), "r"(a[2]), "r"(a[3]), "r"(b0), "r"(b1));
}

// ---------------------------------------------------------------------------
// fp16 GEMM: C[m,n] = sum_k A[m,k] * B[n,k] (+bias), fp32 accumulate.
// TMA SW128 loads, ldmatrix.x4 consumption, mma.sync.m16n8k16 compute.
// 512 threads = 16 warps (4m x 4n), warp tile 32x64, CTA tile 128x256, BK=64.
// grid: x = m-tile (fast -> B-tile L2 sharing), y = n-tile.
// ---------------------------------------------------------------------------
__global__ __launch_bounds__(NTHR, 1)
void gemm_f16(const __grid_constant__ CUtensorMap mapA,
              const __grid_constant__ CUtensorMap mapB,
              float* __restrict__ C, int ldc,
              const float* __restrict__ bias) {
    extern __shared__ __align__(1024) char smem[];
    const uint32_t sb = smem_u32(smem);
    const int tid = threadIdx.x, wid = tid >> 5, lane = tid & 31;
    const int m0 = blockIdx.x * BM_;
    const int n0 = blockIdx.y * BN_;
    const int wm = (wid & 3) * 32;        // warp m offset in CTA tile
    const int wn = (wid >> 2) * 64;       // warp n offset in CTA tile

    const uint32_t FULL = sb;             // NSTG mbarriers, 8B each

    if (tid == 0) {
        #pragma unroll
        for (int s = 0; s < NSTG; ++s) mbar_init(FULL + 8 * s, 1);
    }
    __syncthreads();

    if (tid == 0) {
        #pragma unroll
        for (int s = 0; s < NSTG; ++s) {
            mbar_expect_tx(FULL + 8 * s, ST_BYTES);
            uint32_t sa = sb + SM0 + s * ST_BYTES;
            tma2d(sa,        &mapA, s * BK_, m0, FULL + 8 * s);
            tma2d(sa + ST_A, &mapB, s * BK_, n0, FULL + 8 * s);
        }
    }

    float c[2][8][4];
    #pragma unroll
    for (int mi = 0; mi < 2; ++mi)
        #pragma unroll
        for (int nj = 0; nj < 8; ++nj)
            #pragma unroll
            for (int q = 0; q < 4; ++q) c[mi][nj][q] = 0.f;

    const int lr = lane & 15;     // ldmatrix row within 16
    const int hi = lane >> 4;     // ldmatrix k-chunk select

    // hoisted swizzled ldmatrix offsets (kk enters as a pure XOR of bits 5..6)
    uint32_t offA[2], offB[4];
    #pragma unroll
    for (int mi = 0; mi < 2; ++mi) {
        int r = wm + mi * 16 + lr;
        offA[mi] = (uint32_t)(r * 128 + ((hi ^ (r & 7)) << 4));
    }
    #pragma unroll
    for (int nj = 0; nj < 4; ++nj) {
        int r = wn + nj * 16 + lr;
        offB[nj] = (uint32_t)(ST_A + r * 128 + ((hi ^ (r & 7)) << 4));
    }

    for (int kt = 0; kt < KT_; ++kt) {
        const int s = kt % NSTG;
        mbar_wait(FULL + 8 * s, (kt / NSTG) & 1);
        const uint32_t sa = sb + SM0 + s * ST_BYTES;   // 1024-aligned; XOR below is carry-free

        #pragma unroll
        for (int kk = 0; kk < 4; ++kk) {        // four k16 steps in BK=64
            const uint32_t kx = (uint32_t)(kk << 5);
            uint32_t am[2][4], bt[4][4];
            #pragma unroll
            for (int mi = 0; mi < 2; ++mi)
                ldsm4(am[mi][0], am[mi][1], am[mi][2], am[mi][3], sa + (offA[mi] ^ kx));
            #pragma unroll
            for (int nj = 0; nj < 4; ++nj)
                ldsm4(bt[nj][0], bt[nj][1], bt[nj][2], bt[nj][3], sa + (offB[nj] ^ kx));
            #pragma unroll
            for (int mi = 0; mi < 2; ++mi)
                #pragma unroll
                for (int n8 = 0; n8 < 8; ++n8)
                    mma16816(c[mi][n8], am[mi],
                             bt[n8 >> 1][n8 & 1], bt[n8 >> 1][(n8 & 1) + 2]);
        }

        __syncthreads();   // all warps done with slot s
        if (tid == 0 && kt + NSTG < KT_) {
            mbar_expect_tx(FULL + 8 * s, ST_BYTES);
            uint32_t sn = sb + SM0 + s * ST_BYTES;
            tma2d(sn,        &mapA, (kt + NSTG) * BK_, m0, FULL + 8 * s);
            tma2d(sn + ST_A, &mapB, (kt + NSTG) * BK_, n0, FULL + 8 * s);
        }
    }

    // -------- epilogue: direct register -> global stores --------
    const int r4 = lane >> 2;            // accum row within 8
    const int c2 = (lane & 3) << 1;      // accum col pair
    #pragma unroll
    for (int mi = 0; mi < 2; ++mi) {
        int row0 = m0 + wm + mi * 16 + r4;
        #pragma unroll
        for (int n8 = 0; n8 < 8; ++n8) {
            int col = n0 + wn + n8 * 8 + c2;
            float bx = 0.f, by = 0.f;
            if (bias) { bx = bias[col]; by = bias[col + 1]; }
            float2 v0 = { c[mi][n8][0] + bx, c[mi][n8][1] + by };
            float2 v1 = { c[mi][n8][2] + bx, c[mi][n8][3] + by };
            *reinterpret_cast<float2*>(C + (size_t)row0 * ldc + col) = v0;
            *reinterpret_cast<float2*>(C + (size_t)(row0 + 8) * ldc + col) = v1;
        }
    }
}

// ---------------------------------------------------------------------------
// embed + relu -> fp16 A [M, H]
// ---------------------------------------------------------------------------
__global__ void embed_half_kernel(const int* __restrict__ tgt,
                                  const float* __restrict__ emb) {
    int idx = blockIdx.x * 256 + threadIdx.x;   // over M_*H_/4
    int m = idx >> 7;          // H_/4 = 128 float4 per row
    int q = idx & 127;
    int b = m >> 7, t = m & 127;
    int tok = (t == 0) ? 1 : tgt[b * T_ + t - 1];
    float4 v = reinterpret_cast<const float4*>(emb + (size_t)tok * H_)[q];
    __half2* dst = reinterpret_cast<__half2*>(g_Ahf) + idx * 2;
    dst[0] = __floats2half2_rn(fmaxf(v.x, 0.f), fmaxf(v.y, 0.f));
    dst[1] = __floats2half2_rn(fmaxf(v.z, 0.f), fmaxf(v.w, 0.f));
}

// ---------------------------------------------------------------------------
// weight fp32 -> fp16 (layout identical, pure convert)
// ---------------------------------------------------------------------------
__global__ void wconv_kernel(const float* __restrict__ W, int total4) {
    int idx = blockIdx.x * 256 + threadIdx.x;
    if (idx >= total4) return;
    float4 v = reinterpret_cast<const float4*>(W)[idx];
    __half2* dst = reinterpret_cast<__half2*>(g_Whf) + idx * 2;
    dst[0] = __floats2half2_rn(v.x, v.y);
    dst[1] = __floats2half2_rn(v.z, v.w);
}

// ---------------------------------------------------------------------------
// hb[b][g] = dot(h0[b,:], W_hh[g,:]) + b_ih[g] + b_hh[g]   (fp32, tiny)
// ---------------------------------------------------------------------------
__global__ void hb_kernel(const float* __restrict__ h0,
                          const float* __restrict__ Whh,
                          const float* __restrict__ bih,
                          const float* __restrict__ bhh) {
    int g = blockIdx.x * 8 + threadIdx.y;
    int b = blockIdx.y;
    const float4* hr = reinterpret_cast<const float4*>(h0 + (size_t)b * H_);
    const float4* wr = reinterpret_cast<const float4*>(Whh + (size_t)g * H_);
    float s = 0.f;
    for (int k = threadIdx.x; k < H_ / 4; k += 32) {
        float4 a = hr[k], w = wr[k];
        s += a.x * w.x + a.y * w.y + a.z * w.z + a.w * w.w;
    }
    #pragma unroll
    for (int o = 16; o; o >>= 1) s += __shfl_xor_sync(0xffffffffu, s, o);
    if (threadIdx.x == 0) g_hb[b * G4_ + g] = s + bih[g] + bhh[g];
}

// ---------------------------------------------------------------------------
// LSTM elementwise; writes h (fp16) back to A + h_last/c_last (fp32)
// ---------------------------------------------------------------------------
__global__ void lstm_half_kernel(const float* __restrict__ c0,
                                 float* __restrict__ out_h,
                                 float* __restrict__ out_c) {
    int idx = blockIdx.x * 256 + threadIdx.x;  // over M_*H_
    int m = idx >> 9, j = idx & 511;
    int b = m >> 7, t = m & 127;
    const float* gr  = g_G  + (size_t)m * G4_;
    const float* hbb = g_hb + (size_t)b * G4_;
    float iv = gr[j]          + hbb[j];
    float fv = gr[H_ + j]     + hbb[H_ + j];
    float gv = gr[2 * H_ + j] + hbb[2 * H_ + j];
    float ov = gr[3 * H_ + j] + hbb[3 * H_ + j];
    float c = sigf(fv) * c0[(size_t)b * H_ + j] + sigf(iv) * tanhf(gv);
    float h = sigf(ov) * tanhf(c);
    g_Ahf[(size_t)m * H_ + j] = __float2half(h);
    if (t == T_ - 1) {
        out_h[(size_t)b * H_ + j] = h;
        out_c[(size_t)b * H_ + j] = c;
    }
}

// ---------------------------------------------------------------------------
typedef CUresult (*PFN_tmapEnc)(CUtensorMap*, CUtensorMapDataType, unsigned int, void*,
                                const unsigned long long*, const unsigned long long*,
                                const unsigned int*, const unsigned int*,
                                CUtensorMapInterleave, CUtensorMapSwizzle,
                                CUtensorMapL2promotion, CUtensorMapFloatOOBfill);

extern "C" void kernel_launch(void* const* d_in, const int* in_sizes, int n_in,
                              void* d_out, int out_size) {
    const float* enc_h = (const float*)d_in[1];
    const float* enc_c = (const float*)d_in[2];
    const int*   tgt   = (const int*)  d_in[3];
    const float* emb   = (const float*)d_in[4];
    const float* W_ih  = (const float*)d_in[5];
    const float* W_hh  = (const float*)d_in[6];
    const float* b_ih  = (const float*)d_in[7];
    const float* b_hh  = (const float*)d_in[8];
    const float* W_out = (const float*)d_in[9];
    const float* b_out = (const float*)d_in[10];
    float* out = (float*)d_out;

    static bool inited = false;
    static float* Gp = nullptr;
    static float* dummy = nullptr;
    static CUtensorMap mapA, mapB;
    if (!inited) {
        void* p;
        cudaGetSymbolAddress(&p, g_G);     Gp    = (float*)p;
        cudaGetSymbolAddress(&p, g_dummy); dummy = (float*)p;
        void* pA; cudaGetSymbolAddress(&pA, g_Ahf);
        void* pW; cudaGetSymbolAddress(&pW, g_Whf);

        void* fn = nullptr;
        cudaDriverEntryPointQueryResult qr;
        cudaGetDriverEntryPoint("cuTensorMapEncodeTiled", &fn, cudaEnableDefault, &qr);
        PFN_tmapEnc enc = (PFN_tmapEnc)fn;

        unsigned long long dimsA[2] = { (unsigned long long)H_, (unsigned long long)M_ };
        unsigned long long strA[1]  = { (unsigned long long)H_ * 2 };
        unsigned int boxA[2] = { (unsigned int)BK_, (unsigned int)BM_ };
        unsigned int es[2]   = { 1u, 1u };
        enc(&mapA, CU_TENSOR_MAP_DATA_TYPE_FLOAT16, 2, pA, dimsA, strA, boxA, es,
            CU_TENSOR_MAP_INTERLEAVE_NONE, CU_TENSOR_MAP_SWIZZLE_128B,
            CU_TENSOR_MAP_L2_PROMOTION_L2_128B, CU_TENSOR_MAP_FLOAT_OOB_FILL_NONE);
        unsigned long long dimsB[2] = { (unsigned long long)H_, (unsigned long long)V_ };
        unsigned int boxB[2] = { (unsigned int)BK_, (unsigned int)BN_ };
        enc(&mapB, CU_TENSOR_MAP_DATA_TYPE_FLOAT16, 2, pW, dimsB, strA, boxB, es,
            CU_TENSOR_MAP_INTERLEAVE_NONE, CU_TENSOR_MAP_SWIZZLE_128B,
            CU_TENSOR_MAP_L2_PROMOTION_L2_128B, CU_TENSOR_MAP_FLOAT_OOB_FILL_NONE);

        cudaFuncSetAttribute(gemm_f16, cudaFuncAttributeMaxDynamicSharedMemorySize, SMEM_TOTAL);
        inited = true;
    }

    // output layout: [logits (M_*V_), h_last (L,B,H), c_last (L,B,H)]
    const long long need = (long long)M_ * V_ + 2LL * L_ * B_ * H_;
    float *hl, *cl;
    if ((long long)out_size >= need) {
        hl = out + (size_t)M_ * V_;
        cl = hl + (size_t)L_ * B_ * H_;
    } else {
        hl = dummy;
        cl = dummy + (size_t)L_ * B_ * H_;
    }

    // 1. embedding + relu (fp16 A)
    embed_half_kernel<<<(M_ * H_ / 4) / 256, 256>>>(tgt, emb);

    // 2. two independent single-step LSTM layers
    for (int l = 0; l < L_; ++l) {
        hb_kernel<<<dim3(G4_ / 8, B_), dim3(32, 8)>>>(
            enc_h + (size_t)l * B_ * H_, W_hh + (size_t)l * G4_ * H_,
            b_ih + (size_t)l * G4_, b_hh + (size_t)l * G4_);
        wconv_kernel<<<((G4_ * H_ / 4) + 255) / 256, 256>>>(
            W_ih + (size_t)l * G4_ * H_, G4_ * H_ / 4);
        gemm_f16<<<dim3(M_ / BM_, G4_ / BN_), NTHR, SMEM_TOTAL>>>(
            mapA, mapB, Gp, G4_, nullptr);
        lstm_half_kernel<<<(M_ * H_) / 256, 256>>>(
            enc_c + (size_t)l * B_ * H_,
            hl + (size_t)l * B_ * H_, cl + (size_t)l * B_ * H_);
    }

    // 3. output projection: logits = X2 * W_out^T + b_out
    wconv_kernel<<<((V_ * H_ / 4) + 255) / 256, 256>>>(W_out, V_ * H_ / 4);
    gemm_f16<<<dim3(M_ / BM_, V_ / BN_), NTHR, SMEM_TOTAL>>>(
        mapA, mapB, out, V_, b_out);
}

// round 6
// speedup vs baseline: 1.0710x; 1.0710x over previous
#include <cuda_runtime.h>
#include <cuda_fp16.h>
#include <cuda.h>
#include <cstdint>

// ---------------- problem constants ----------------
#define B_    16
#define T_    128
#define H_    512
#define L_    2
#define V_    32000
#define M_    (B_ * T_)        // 2048
#define G4_   (4 * H_)         // 2048

// ---------------- GEMM tiling ----------------
#define BM_   128
#define BN_   256
#define BK_   64               // fp16 = 128 bytes/row = SW128 atom
#define KT_   (H_ / BK_)       // 8 k-tiles
#define NSTG  4
#define ST_A  (BM_ * BK_ * 2)  // 16384
#define ST_B  (BN_ * BK_ * 2)  // 32768
#define ST_BYTES (ST_A + ST_B) // 49152
#define SM0   1024
#define SMEM_TOTAL (SM0 + NSTG * ST_BYTES)   // 197632
#define NTHR  512              // 16 warps: 4 m-warps x 4 n-warps, warp tile 32x64
#define NWARP (NTHR / 32)

// ---------------- scratch (static device globals) ----------------
__device__ __align__(128) __half g_Ahf[(size_t)M_ * H_];
__device__ __align__(128) __half g_Whf[(size_t)V_ * H_];
__device__ float g_G [(size_t)M_ * G4_];
__device__ float g_hb[B_ * G4_];
__device__ float g_dummy[2 * L_ * B_ * H_];

__device__ __forceinline__ float sigf(float x) { return 1.0f / (1.0f + expf(-x)); }

// ---------------- PTX helpers (base ISA only; no tcgen05 on sm_103 target) ----
__device__ __forceinline__ uint32_t smem_u32(const void* p) {
    uint32_t a;
    asm("{ .reg .u64 t; cvta.to.shared.u64 t, %1; cvt.u32.u64 %0, t; }" : "=r"(a) : "l"(p));
    return a;
}
__device__ __forceinline__ bool elect1() {
    uint32_t p;
    asm volatile("{ .reg .pred p; elect.sync _|p, 0xFFFFFFFF; selp.b32 %0, 1, 0, p; }" : "=r"(p));
    return p != 0;
}
__device__ __forceinline__ void mbar_init(uint32_t a, uint32_t c) {
    asm volatile("mbarrier.init.shared.b64 [%0], %1;" :: "r"(a), "r"(c) : "memory");
}
__device__ __forceinline__ void mbar_arrive(uint32_t a) {
    asm volatile("mbarrier.arrive.shared.b64 _, [%0];" :: "r"(a) : "memory");
}
__device__ __forceinline__ void mbar_expect_tx(uint32_t a, uint32_t b) {
    asm volatile("mbarrier.arrive.expect_tx.shared.b64 _, [%0], %1;" :: "r"(a), "r"(b) : "memory");
}
__device__ __forceinline__ void mbar_wait(uint32_t a, uint32_t ph) {
    asm volatile(
        "{ .reg .pred P;\n"
        "WL_%=: mbarrier.try_wait.parity.acquire.cta.shared::cta.b64 P, [%0], %1, 0x989680;\n"
        "@P bra.uni WD_%=;\n"
        "bra.uni WL_%=;\n"
        "WD_%=: }" :: "r"(a), "r"(ph) : "memory");
}
__device__ __forceinline__ void tma2d(uint32_t dst, const CUtensorMap* m, int x, int y, uint32_t mbar) {
    asm volatile(
        "cp.async.bulk.tensor.2d.shared::cta.global.tile.mbarrier::complete_tx::bytes "
        "[%0], [%1, {%2, %3}], [%4];"
        :: "r"(dst), "l"(m), "r"(x), "r"(y), "r"(mbar) : "memory");
}
__device__ __forceinline__ void ldsm4(uint32_t& r0, uint32_t& r1, uint32_t& r2, uint32_t& r3,
                                      uint32_t addr) {
    asm volatile("ldmatrix.sync.aligned.m8n8.x4.shared.b16 {%0,%1,%2,%3}, [%4];"
                 : "=r"(r0), "=r"(r1), "=r"(r2), "=r"(r3) : "r"(addr));
}
__device__ __forceinline__ void mma16816(float* c, const uint32_t* a, uint32_t b0, uint32_t b1) {
    asm volatile(
        "mma.sync.aligned.m16n8k16.row.col.f32.f16.f16.f32 "
        "{%0,%1,%2,%3}, {%4,%5,%6,%7}, {%8,%9}, {%0,%1,%2,%3};"
        : "+f"(c[0]), "+f"(c[1]), "+f"(c[2]), "+f"(c[3])
        : "r"(a[0]), "r"(a[1]), "r"(a[2]), "r"(a[3]), "r"(b0), "r"(b1));
}

// ---------------------------------------------------------------------------
// fp16 GEMM: C[m,n] = sum_k A[m,k] * B[n,k] (+bias), fp32 accumulate.
// Fully asynchronous consumer pipeline: no __syncthreads in the mainloop.
// FULL[s]: tx-count mbarrier (TMA completion). EMPTY[s]: arrive-count = 16
// warps; producer (warp0 elected lane) waits EMPTY before refilling a slot.
// Warps drift up to NSTG-1 stages apart -> cross-kt LDSM/HMMA overlap.
// 512 threads = 16 warps (4m x 4n), warp tile 32x64, CTA tile 128x256, BK=64.
// ---------------------------------------------------------------------------
__global__ __launch_bounds__(NTHR, 1)
void gemm_f16(const __grid_constant__ CUtensorMap mapA,
              const __grid_constant__ CUtensorMap mapB,
              float* __restrict__ C, int ldc,
              const float* __restrict__ bias) {
    extern __shared__ __align__(1024) char smem[];
    const uint32_t sb = smem_u32(smem);
    const int tid = threadIdx.x, wid = tid >> 5, lane = tid & 31;
    const int m0 = blockIdx.x * BM_;
    const int n0 = blockIdx.y * BN_;
    const int wm = (wid & 3) * 32;        // warp m offset in CTA tile
    const int wn = (wid >> 2) * 64;       // warp n offset in CTA tile

    const uint32_t FULL  = sb;                // NSTG x 8B
    const uint32_t EMPTY = sb + 8 * NSTG;     // NSTG x 8B

    if (tid == 0) {
        #pragma unroll
        for (int s = 0; s < NSTG; ++s) {
            mbar_init(FULL + 8 * s, 1);
            mbar_init(EMPTY + 8 * s, NWARP);
        }
    }
    __syncthreads();

    if (tid == 0) {
        #pragma unroll
        for (int s = 0; s < NSTG; ++s) {
            mbar_expect_tx(FULL + 8 * s, ST_BYTES);
            uint32_t sa = sb + SM0 + s * ST_BYTES;
            tma2d(sa,        &mapA, s * BK_, m0, FULL + 8 * s);
            tma2d(sa + ST_A, &mapB, s * BK_, n0, FULL + 8 * s);
        }
    }

    float c[2][8][4];
    #pragma unroll
    for (int mi = 0; mi < 2; ++mi)
        #pragma unroll
        for (int nj = 0; nj < 8; ++nj)
            #pragma unroll
            for (int q = 0; q < 4; ++q) c[mi][nj][q] = 0.f;

    const int lr = lane & 15;     // ldmatrix row within 16
    const int hi = lane >> 4;     // ldmatrix k-chunk select

    // hoisted swizzled ldmatrix offsets (kk enters as a pure XOR of bits 5..6)
    uint32_t offA[2], offB[4];
    #pragma unroll
    for (int mi = 0; mi < 2; ++mi) {
        int r = wm + mi * 16 + lr;
        offA[mi] = (uint32_t)(r * 128 + ((hi ^ (r & 7)) << 4));
    }
    #pragma unroll
    for (int nj = 0; nj < 4; ++nj) {
        int r = wn + nj * 16 + lr;
        offB[nj] = (uint32_t)(ST_A + r * 128 + ((hi ^ (r & 7)) << 4));
    }

    const bool producer = (wid == 0) && elect1();

    for (int kt = 0; kt < KT_; ++kt) {
        const int s = kt % NSTG;
        mbar_wait(FULL + 8 * s, (kt / NSTG) & 1);
        const uint32_t sa = sb + SM0 + s * ST_BYTES;   // 1024-aligned; XOR below carry-free

        #pragma unroll
        for (int kk = 0; kk < 4; ++kk) {        // four k16 steps in BK=64
            const uint32_t kx = (uint32_t)(kk << 5);
            uint32_t am[2][4], bt[4][4];
            #pragma unroll
            for (int mi = 0; mi < 2; ++mi)
                ldsm4(am[mi][0], am[mi][1], am[mi][2], am[mi][3], sa + (offA[mi] ^ kx));
            #pragma unroll
            for (int nj = 0; nj < 4; ++nj)
                ldsm4(bt[nj][0], bt[nj][1], bt[nj][2], bt[nj][3], sa + (offB[nj] ^ kx));
            #pragma unroll
            for (int mi = 0; mi < 2; ++mi)
                #pragma unroll
                for (int n8 = 0; n8 < 8; ++n8)
                    mma16816(c[mi][n8], am[mi],
                             bt[n8 >> 1][n8 & 1], bt[n8 >> 1][(n8 & 1) + 2]);
        }

        // this warp is done reading slot s (volatile asm order keeps this
        // after the LDSMs above; their smem reads are long complete before
        // the producer can possibly re-fill the slot)
        if (lane == 0) mbar_arrive(EMPTY + 8 * s);

        // producer: refill slot s with tile kt+NSTG once all 16 warps drained it
        if (producer && kt + NSTG < KT_) {
            mbar_wait(EMPTY + 8 * s, (kt / NSTG) & 1);
            mbar_expect_tx(FULL + 8 * s, ST_BYTES);
            uint32_t sn = sb + SM0 + s * ST_BYTES;
            tma2d(sn,        &mapA, (kt + NSTG) * BK_, m0, FULL + 8 * s);
            tma2d(sn + ST_A, &mapB, (kt + NSTG) * BK_, n0, FULL + 8 * s);
        }
    }

    // -------- epilogue: direct register -> global stores (no smem use) ------
    const int r4 = lane >> 2;            // accum row within 8
    const int c2 = (lane & 3) << 1;      // accum col pair
    #pragma unroll
    for (int mi = 0; mi < 2; ++mi) {
        int row0 = m0 + wm + mi * 16 + r4;
        #pragma unroll
        for (int n8 = 0; n8 < 8; ++n8) {
            int col = n0 + wn + n8 * 8 + c2;
            float bx = 0.f, by = 0.f;
            if (bias) { bx = bias[col]; by = bias[col + 1]; }
            float2 v0 = { c[mi][n8][0] + bx, c[mi][n8][1] + by };
            float2 v1 = { c[mi][n8][2] + bx, c[mi][n8][3] + by };
            *reinterpret_cast<float2*>(C + (size_t)row0 * ldc + col) = v0;
            *reinterpret_cast<float2*>(C + (size_t)(row0 + 8) * ldc + col) = v1;
        }
    }
}

// ---------------------------------------------------------------------------
// embed + relu -> fp16 A [M, H]
// ---------------------------------------------------------------------------
__global__ void embed_half_kernel(const int* __restrict__ tgt,
                                  const float* __restrict__ emb) {
    int idx = blockIdx.x * 256 + threadIdx.x;   // over M_*H_/4
    int m = idx >> 7;          // H_/4 = 128 float4 per row
    int q = idx & 127;
    int b = m >> 7, t = m & 127;
    int tok = (t == 0) ? 1 : tgt[b * T_ + t - 1];
    float4 v = reinterpret_cast<const float4*>(emb + (size_t)tok * H_)[q];
    __half2* dst = reinterpret_cast<__half2*>(g_Ahf) + idx * 2;
    dst[0] = __floats2half2_rn(fmaxf(v.x, 0.f), fmaxf(v.y, 0.f));
    dst[1] = __floats2half2_rn(fmaxf(v.z, 0.f), fmaxf(v.w, 0.f));
}

// ---------------------------------------------------------------------------
// weight fp32 -> fp16 (layout identical, pure convert)
// ---------------------------------------------------------------------------
__global__ void wconv_kernel(const float* __restrict__ W, int total4) {
    int idx = blockIdx.x * 256 + threadIdx.x;
    if (idx >= total4) return;
    float4 v = reinterpret_cast<const float4*>(W)[idx];
    __half2* dst = reinterpret_cast<__half2*>(g_Whf) + idx * 2;
    dst[0] = __floats2half2_rn(v.x, v.y);
    dst[1] = __floats2half2_rn(v.z, v.w);
}

// ---------------------------------------------------------------------------
// hb[b][g] = dot(h0[b,:], W_hh[g,:]) + b_ih[g] + b_hh[g]   (fp32, tiny)
// ---------------------------------------------------------------------------
__global__ void hb_kernel(const float* __restrict__ h0,
                          const float* __restrict__ Whh,
                          const float* __restrict__ bih,
                          const float* __restrict__ bhh) {
    int g = blockIdx.x * 8 + threadIdx.y;
    int b = blockIdx.y;
    const float4* hr = reinterpret_cast<const float4*>(h0 + (size_t)b * H_);
    const float4* wr = reinterpret_cast<const float4*>(Whh + (size_t)g * H_);
    float s = 0.f;
    for (int k = threadIdx.x; k < H_ / 4; k += 32) {
        float4 a = hr[k], w = wr[k];
        s += a.x * w.x + a.y * w.y + a.z * w.z + a.w * w.w;
    }
    #pragma unroll
    for (int o = 16; o; o >>= 1) s += __shfl_xor_sync(0xffffffffu, s, o);
    if (threadIdx.x == 0) g_hb[b * G4_ + g] = s + bih[g] + bhh[g];
}

// ---------------------------------------------------------------------------
// LSTM elementwise; writes h (fp16) back to A + h_last/c_last (fp32)
// ---------------------------------------------------------------------------
__global__ void lstm_half_kernel(const float* __restrict__ c0,
                                 float* __restrict__ out_h,
                                 float* __restrict__ out_c) {
    int idx = blockIdx.x * 256 + threadIdx.x;  // over M_*H_
    int m = idx >> 9, j = idx & 511;
    int b = m >> 7, t = m & 127;
    const float* gr  = g_G  + (size_t)m * G4_;
    const float* hbb = g_hb + (size_t)b * G4_;
    float iv = gr[j]          + hbb[j];
    float fv = gr[H_ + j]     + hbb[H_ + j];
    float gv = gr[2 * H_ + j] + hbb[2 * H_ + j];
    float ov = gr[3 * H_ + j] + hbb[3 * H_ + j];
    float c = sigf(fv) * c0[(size_t)b * H_ + j] + sigf(iv) * tanhf(gv);
    float h = sigf(ov) * tanhf(c);
    g_Ahf[(size_t)m * H_ + j] = __float2half(h);
    if (t == T_ - 1) {
        out_h[(size_t)b * H_ + j] = h;
        out_c[(size_t)b * H_ + j] = c;
    }
}

// ---------------------------------------------------------------------------
typedef CUresult (*PFN_tmapEnc)(CUtensorMap*, CUtensorMapDataType, unsigned int, void*,
                                const unsigned long long*, const unsigned long long*,
                                const unsigned int*, const unsigned int*,
                                CUtensorMapInterleave, CUtensorMapSwizzle,
                                CUtensorMapL2promotion, CUtensorMapFloatOOBfill);

extern "C" void kernel_launch(void* const* d_in, const int* in_sizes, int n_in,
                              void* d_out, int out_size) {
    const float* enc_h = (const float*)d_in[1];
    const float* enc_c = (const float*)d_in[2];
    const int*   tgt   = (const int*)  d_in[3];
    const float* emb   = (const float*)d_in[4];
    const float* W_ih  = (const float*)d_in[5];
    const float* W_hh  = (const float*)d_in[6];
    const float* b_ih  = (const float*)d_in[7];
    const float* b_hh  = (const float*)d_in[8];
    const float* W_out = (const float*)d_in[9];
    const float* b_out = (const float*)d_in[10];
    float* out = (float*)d_out;

    static bool inited = false;
    static float* Gp = nullptr;
    static float* dummy = nullptr;
    static CUtensorMap mapA, mapB;
    if (!inited) {
        void* p;
        cudaGetSymbolAddress(&p, g_G);     Gp    = (float*)p;
        cudaGetSymbolAddress(&p, g_dummy); dummy = (float*)p;
        void* pA; cudaGetSymbolAddress(&pA, g_Ahf);
        void* pW; cudaGetSymbolAddress(&pW, g_Whf);

        void* fn = nullptr;
        cudaDriverEntryPointQueryResult qr;
        cudaGetDriverEntryPoint("cuTensorMapEncodeTiled", &fn, cudaEnableDefault, &qr);
        PFN_tmapEnc enc = (PFN_tmapEnc)fn;

        unsigned long long dimsA[2] = { (unsigned long long)H_, (unsigned long long)M_ };
        unsigned long long strA[1]  = { (unsigned long long)H_ * 2 };
        unsigned int boxA[2] = { (unsigned int)BK_, (unsigned int)BM_ };
        unsigned int es[2]   = { 1u, 1u };
        enc(&mapA, CU_TENSOR_MAP_DATA_TYPE_FLOAT16, 2, pA, dimsA, strA, boxA, es,
            CU_TENSOR_MAP_INTERLEAVE_NONE, CU_TENSOR_MAP_SWIZZLE_128B,
            CU_TENSOR_MAP_L2_PROMOTION_L2_128B, CU_TENSOR_MAP_FLOAT_OOB_FILL_NONE);
        unsigned long long dimsB[2] = { (unsigned long long)H_, (unsigned long long)V_ };
        unsigned int boxB[2] = { (unsigned int)BK_, (unsigned int)BN_ };
        enc(&mapB, CU_TENSOR_MAP_DATA_TYPE_FLOAT16, 2, pW, dimsB, strA, boxB, es,
            CU_TENSOR_MAP_INTERLEAVE_NONE, CU_TENSOR_MAP_SWIZZLE_128B,
            CU_TENSOR_MAP_L2_PROMOTION_L2_128B, CU_TENSOR_MAP_FLOAT_OOB_FILL_NONE);

        cudaFuncSetAttribute(gemm_f16, cudaFuncAttributeMaxDynamicSharedMemorySize, SMEM_TOTAL);
        inited = true;
    }

    // output layout: [logits (M_*V_), h_last (L,B,H), c_last (L,B,H)]
    const long long need = (long long)M_ * V_ + 2LL * L_ * B_ * H_;
    float *hl, *cl;
    if ((long long)out_size >= need) {
        hl = out + (size_t)M_ * V_;
        cl = hl + (size_t)L_ * B_ * H_;
    } else {
        hl = dummy;
        cl = dummy + (size_t)L_ * B_ * H_;
    }

    // 1. embedding + relu (fp16 A)
    embed_half_kernel<<<(M_ * H_ / 4) / 256, 256>>>(tgt, emb);

    // 2. two independent single-step LSTM layers
    for (int l = 0; l < L_; ++l) {
        hb_kernel<<<dim3(G4_ / 8, B_), dim3(32, 8)>>>(
            enc_h + (size_t)l * B_ * H_, W_hh + (size_t)l * G4_ * H_,
            b_ih + (size_t)l * G4_, b_hh + (size_t)l * G4_);
        wconv_kernel<<<((G4_ * H_ / 4) + 255) / 256, 256>>>(
            W_ih + (size_t)l * G4_ * H_, G4_ * H_ / 4);
        gemm_f16<<<dim3(M_ / BM_, G4_ / BN_), NTHR, SMEM_TOTAL>>>(
            mapA, mapB, Gp, G4_, nullptr);
        lstm_half_kernel<<<(M_ * H_) / 256, 256>>>(
            enc_c + (size_t)l * B_ * H_,
            hl + (size_t)l * B_ * H_, cl + (size_t)l * B_ * H_);
    }

    // 3. output projection: logits = X2 * W_out^T + b_out
    wconv_kernel<<<((V_ * H_ / 4) + 255) / 256, 256>>>(W_out, V_ * H_ / 4);
    gemm_f16<<<dim3(M_ / BM_, V_ / BN_), NTHR, SMEM_TOTAL>>>(
        mapA, mapB, out, V_, b_out);
}

// round 7
// speedup vs baseline: 1.1669x; 1.0896x over previous
#include <cuda_runtime.h>
#include <cuda_fp16.h>
#include <cuda.h>
#include <cstdint>

// ---------------- problem constants ----------------
#define B_    16
#define T_    128
#define H_    512
#define L_    2
#define V_    32000
#define M_    (B_ * T_)        // 2048
#define G4_   (4 * H_)         // 2048

// ---------------- GEMM tiling ----------------
#define BM_   128
#define BN_   128
#define BK_   64               // fp16 = 128 bytes/row = SW128 atom
#define KT_   (H_ / BK_)       // 8 k-tiles
#define NSTG  3
#define ST_A  (BM_ * BK_ * 2)  // 16384
#define ST_B  (BN_ * BK_ * 2)  // 16384
#define ST_BYTES (ST_A + ST_B) // 32768
#define SM0   1024
#define SMEM_TOTAL (SM0 + NSTG * ST_BYTES)   // 99328 -> 2 CTAs/SM
#define NTHR  256              // 8 warps: 4 m-warps x 2 n-warps, warp tile 32x64
#define NWARP (NTHR / 32)

// ---------------- scratch (static device globals) ----------------
__device__ __align__(128) __half g_Ahf[(size_t)M_ * H_];
__device__ __align__(128) __half g_Whf[(size_t)V_ * H_];
__device__ float g_G [(size_t)M_ * G4_];
__device__ float g_hb[B_ * G4_];
__device__ float g_dummy[2 * L_ * B_ * H_];

__device__ __forceinline__ float sigf(float x) { return 1.0f / (1.0f + expf(-x)); }

// ---------------- PTX helpers (base ISA only; no tcgen05 on sm_103 target) ----
__device__ __forceinline__ uint32_t smem_u32(const void* p) {
    uint32_t a;
    asm("{ .reg .u64 t; cvta.to.shared.u64 t, %1; cvt.u32.u64 %0, t; }" : "=r"(a) : "l"(p));
    return a;
}
__device__ __forceinline__ bool elect1() {
    uint32_t p;
    asm volatile("{ .reg .pred p; elect.sync _|p, 0xFFFFFFFF; selp.b32 %0, 1, 0, p; }" : "=r"(p));
    return p != 0;
}
__device__ __forceinline__ void mbar_init(uint32_t a, uint32_t c) {
    asm volatile("mbarrier.init.shared.b64 [%0], %1;" :: "r"(a), "r"(c) : "memory");
}
__device__ __forceinline__ void mbar_arrive(uint32_t a) {
    asm volatile("mbarrier.arrive.shared.b64 _, [%0];" :: "r"(a) : "memory");
}
__device__ __forceinline__ void mbar_expect_tx(uint32_t a, uint32_t b) {
    asm volatile("mbarrier.arrive.expect_tx.shared.b64 _, [%0], %1;" :: "r"(a), "r"(b) : "memory");
}
__device__ __forceinline__ void mbar_wait(uint32_t a, uint32_t ph) {
    asm volatile(
        "{ .reg .pred P;\n"
        "WL_%=: mbarrier.try_wait.parity.acquire.cta.shared::cta.b64 P, [%0], %1, 0x989680;\n"
        "@P bra.uni WD_%=;\n"
        "bra.uni WL_%=;\n"
        "WD_%=: }" :: "r"(a), "r"(ph) : "memory");
}
__device__ __forceinline__ void tma2d(uint32_t dst, const CUtensorMap* m, int x, int y, uint32_t mbar) {
    asm volatile(
        "cp.async.bulk.tensor.2d.shared::cta.global.tile.mbarrier::complete_tx::bytes "
        "[%0], [%1, {%2, %3}], [%4];"
        :: "r"(dst), "l"(m), "r"(x), "r"(y), "r"(mbar) : "memory");
}
__device__ __forceinline__ void ldsm4(uint32_t& r0, uint32_t& r1, uint32_t& r2, uint32_t& r3,
                                      uint32_t addr) {
    asm volatile("ldmatrix.sync.aligned.m8n8.x4.shared.b16 {%0,%1,%2,%3}, [%4];"
                 : "=r"(r0), "=r"(r1), "=r"(r2), "=r"(r3) : "r"(addr));
}
__device__ __forceinline__ void mma16816(float* c, const uint32_t* a, uint32_t b0, uint32_t b1) {
    asm volatile(
        "mma.sync.aligned.m16n8k16.row.col.f32.f16.f16.f32 "
        "{%0,%1,%2,%3}, {%4,%5,%6,%7}, {%8,%9}, {%0,%1,%2,%3};"
        : "+f"(c[0]), "+f"(c[1]), "+f"(c[2]), "+f"(c[3])
        : "r"(a[0]), "r"(a[1]), "r"(a[2]), "r"(a[3]), "r"(b0), "r"(b1));
}

// ---------------------------------------------------------------------------
// fp16 GEMM: C[m,n] = sum_k A[m,k] * B[n,k] (+bias), fp32 accumulate.
// CTA tile 128x128, 256 threads (8 warps, 4m x 2n, warp tile 32x64).
// 2 CTAs resident per SM (97KB smem, <=128 regs) -> cross-CTA latency hiding:
// while one CTA's warps wait on TMA/barriers or burst on the smem crossbar,
// the co-resident CTA keeps the tensor pipe busy.
// Async consumer pipeline (FULL tx-barriers + EMPTY arrive-barriers), no
// __syncthreads in the mainloop.
// ---------------------------------------------------------------------------
__global__ __launch_bounds__(NTHR, 2)
void gemm_f16(const __grid_constant__ CUtensorMap mapA,
              const __grid_constant__ CUtensorMap mapB,
              float* __restrict__ C, int ldc,
              const float* __restrict__ bias) {
    extern __shared__ __align__(1024) char smem[];
    const uint32_t sb = smem_u32(smem);
    const int tid = threadIdx.x, wid = tid >> 5, lane = tid & 31;
    const int m0 = blockIdx.x * BM_;
    const int n0 = blockIdx.y * BN_;
    const int wm = (wid & 3) * 32;        // warp m offset in CTA tile
    const int wn = (wid >> 2) * 64;       // warp n offset in CTA tile

    const uint32_t FULL  = sb;                // NSTG x 8B
    const uint32_t EMPTY = sb + 8 * NSTG;     // NSTG x 8B

    if (tid == 0) {
        #pragma unroll
        for (int s = 0; s < NSTG; ++s) {
            mbar_init(FULL + 8 * s, 1);
            mbar_init(EMPTY + 8 * s, NWARP);
        }
    }
    __syncthreads();

    if (tid == 0) {
        #pragma unroll
        for (int s = 0; s < NSTG; ++s) {
            mbar_expect_tx(FULL + 8 * s, ST_BYTES);
            uint32_t sa = sb + SM0 + s * ST_BYTES;
            tma2d(sa,        &mapA, s * BK_, m0, FULL + 8 * s);
            tma2d(sa + ST_A, &mapB, s * BK_, n0, FULL + 8 * s);
        }
    }

    float c[2][8][4];
    #pragma unroll
    for (int mi = 0; mi < 2; ++mi)
        #pragma unroll
        for (int nj = 0; nj < 8; ++nj)
            #pragma unroll
            for (int q = 0; q < 4; ++q) c[mi][nj][q] = 0.f;

    const int lr = lane & 15;     // ldmatrix row within 16
    const int hi = lane >> 4;     // ldmatrix k-chunk select

    // hoisted swizzled ldmatrix offsets (kk enters as a pure XOR of bits 5..6)
    uint32_t offA[2], offB[4];
    #pragma unroll
    for (int mi = 0; mi < 2; ++mi) {
        int r = wm + mi * 16 + lr;
        offA[mi] = (uint32_t)(r * 128 + ((hi ^ (r & 7)) << 4));
    }
    #pragma unroll
    for (int nj = 0; nj < 4; ++nj) {
        int r = wn + nj * 16 + lr;
        offB[nj] = (uint32_t)(ST_A + r * 128 + ((hi ^ (r & 7)) << 4));
    }

    const bool producer = (wid == 0) && elect1();

    for (int kt = 0; kt < KT_; ++kt) {
        const int s = kt % NSTG;
        mbar_wait(FULL + 8 * s, (kt / NSTG) & 1);
        const uint32_t sa = sb + SM0 + s * ST_BYTES;   // 1024-aligned; XOR below carry-free

        #pragma unroll
        for (int kk = 0; kk < 4; ++kk) {        // four k16 steps in BK=64
            const uint32_t kx = (uint32_t)(kk << 5);
            uint32_t am[2][4], bt[4][4];
            #pragma unroll
            for (int mi = 0; mi < 2; ++mi)
                ldsm4(am[mi][0], am[mi][1], am[mi][2], am[mi][3], sa + (offA[mi] ^ kx));
            #pragma unroll
            for (int nj = 0; nj < 4; ++nj)
                ldsm4(bt[nj][0], bt[nj][1], bt[nj][2], bt[nj][3], sa + (offB[nj] ^ kx));
            #pragma unroll
            for (int mi = 0; mi < 2; ++mi)
                #pragma unroll
                for (int n8 = 0; n8 < 8; ++n8)
                    mma16816(c[mi][n8], am[mi],
                             bt[n8 >> 1][n8 & 1], bt[n8 >> 1][(n8 & 1) + 2]);
        }

        // this warp is done reading slot s
        if (lane == 0) mbar_arrive(EMPTY + 8 * s);

        // producer: refill slot s with tile kt+NSTG once all warps drained it
        if (producer && kt + NSTG < KT_) {
            mbar_wait(EMPTY + 8 * s, (kt / NSTG) & 1);
            mbar_expect_tx(FULL + 8 * s, ST_BYTES);
            uint32_t sn = sb + SM0 + s * ST_BYTES;
            tma2d(sn,        &mapA, (kt + NSTG) * BK_, m0, FULL + 8 * s);
            tma2d(sn + ST_A, &mapB, (kt + NSTG) * BK_, n0, FULL + 8 * s);
        }
    }

    // -------- epilogue: direct register -> global stores (no smem use) ------
    const int r4 = lane >> 2;            // accum row within 8
    const int c2 = (lane & 3) << 1;      // accum col pair
    #pragma unroll
    for (int mi = 0; mi < 2; ++mi) {
        int row0 = m0 + wm + mi * 16 + r4;
        #pragma unroll
        for (int n8 = 0; n8 < 8; ++n8) {
            int col = n0 + wn + n8 * 8 + c2;
            float bx = 0.f, by = 0.f;
            if (bias) { bx = bias[col]; by = bias[col + 1]; }
            float2 v0 = { c[mi][n8][0] + bx, c[mi][n8][1] + by };
            float2 v1 = { c[mi][n8][2] + bx, c[mi][n8][3] + by };
            *reinterpret_cast<float2*>(C + (size_t)row0 * ldc + col) = v0;
            *reinterpret_cast<float2*>(C + (size_t)(row0 + 8) * ldc + col) = v1;
        }
    }
}

// ---------------------------------------------------------------------------
// embed + relu -> fp16 A [M, H]
// ---------------------------------------------------------------------------
__global__ void embed_half_kernel(const int* __restrict__ tgt,
                                  const float* __restrict__ emb) {
    int idx = blockIdx.x * 256 + threadIdx.x;   // over M_*H_/4
    int m = idx >> 7;          // H_/4 = 128 float4 per row
    int q = idx & 127;
    int b = m >> 7, t = m & 127;
    int tok = (t == 0) ? 1 : tgt[b * T_ + t - 1];
    float4 v = reinterpret_cast<const float4*>(emb + (size_t)tok * H_)[q];
    __half2* dst = reinterpret_cast<__half2*>(g_Ahf) + idx * 2;
    dst[0] = __floats2half2_rn(fmaxf(v.x, 0.f), fmaxf(v.y, 0.f));
    dst[1] = __floats2half2_rn(fmaxf(v.z, 0.f), fmaxf(v.w, 0.f));
}

// ---------------------------------------------------------------------------
// weight fp32 -> fp16 (layout identical, pure convert)
// ---------------------------------------------------------------------------
__global__ void wconv_kernel(const float* __restrict__ W, int total4) {
    int idx = blockIdx.x * 256 + threadIdx.x;
    if (idx >= total4) return;
    float4 v = reinterpret_cast<const float4*>(W)[idx];
    __half2* dst = reinterpret_cast<__half2*>(g_Whf) + idx * 2;
    dst[0] = __floats2half2_rn(v.x, v.y);
    dst[1] = __floats2half2_rn(v.z, v.w);
}

// ---------------------------------------------------------------------------
// hb[b][g] = dot(h0[b,:], W_hh[g,:]) + b_ih[g] + b_hh[g]   (fp32, tiny)
// ---------------------------------------------------------------------------
__global__ void hb_kernel(const float* __restrict__ h0,
                          const float* __restrict__ Whh,
                          const float* __restrict__ bih,
                          const float* __restrict__ bhh) {
    int g = blockIdx.x * 8 + threadIdx.y;
    int b = blockIdx.y;
    const float4* hr = reinterpret_cast<const float4*>(h0 + (size_t)b * H_);
    const float4* wr = reinterpret_cast<const float4*>(Whh + (size_t)g * H_);
    float s = 0.f;
    for (int k = threadIdx.x; k < H_ / 4; k += 32) {
        float4 a = hr[k], w = wr[k];
        s += a.x * w.x + a.y * w.y + a.z * w.z + a.w * w.w;
    }
    #pragma unroll
    for (int o = 16; o; o >>= 1) s += __shfl_xor_sync(0xffffffffu, s, o);
    if (threadIdx.x == 0) g_hb[b * G4_ + g] = s + bih[g] + bhh[g];
}

// ---------------------------------------------------------------------------
// LSTM elementwise; writes h (fp16) back to A + h_last/c_last (fp32)
// ---------------------------------------------------------------------------
__global__ void lstm_half_kernel(const float* __restrict__ c0,
                                 float* __restrict__ out_h,
                                 float* __restrict__ out_c) {
    int idx = blockIdx.x * 256 + threadIdx.x;  // over M_*H_
    int m = idx >> 9, j = idx & 511;
    int b = m >> 7, t = m & 127;
    const float* gr  = g_G  + (size_t)m * G4_;
    const float* hbb = g_hb + (size_t)b * G4_;
    float iv = gr[j]          + hbb[j];
    float fv = gr[H_ + j]     + hbb[H_ + j];
    float gv = gr[2 * H_ + j] + hbb[2 * H_ + j];
    float ov = gr[3 * H_ + j] + hbb[3 * H_ + j];
    float c = sigf(fv) * c0[(size_t)b * H_ + j] + sigf(iv) * tanhf(gv);
    float h = sigf(ov) * tanhf(c);
    g_Ahf[(size_t)m * H_ + j] = __float2half(h);
    if (t == T_ - 1) {
        out_h[(size_t)b * H_ + j] = h;
        out_c[(size_t)b * H_ + j] = c;
    }
}

// ---------------------------------------------------------------------------
typedef CUresult (*PFN_tmapEnc)(CUtensorMap*, CUtensorMapDataType, unsigned int, void*,
                                const unsigned long long*, const unsigned long long*,
                                const unsigned int*, const unsigned int*,
                                CUtensorMapInterleave, CUtensorMapSwizzle,
                                CUtensorMapL2promotion, CUtensorMapFloatOOBfill);

extern "C" void kernel_launch(void* const* d_in, const int* in_sizes, int n_in,
                              void* d_out, int out_size) {
    const float* enc_h = (const float*)d_in[1];
    const float* enc_c = (const float*)d_in[2];
    const int*   tgt   = (const int*)  d_in[3];
    const float* emb   = (const float*)d_in[4];
    const float* W_ih  = (const float*)d_in[5];
    const float* W_hh  = (const float*)d_in[6];
    const float* b_ih  = (const float*)d_in[7];
    const float* b_hh  = (const float*)d_in[8];
    const float* W_out = (const float*)d_in[9];
    const float* b_out = (const float*)d_in[10];
    float* out = (float*)d_out;

    static bool inited = false;
    static float* Gp = nullptr;
    static float* dummy = nullptr;
    static CUtensorMap mapA, mapB;
    if (!inited) {
        void* p;
        cudaGetSymbolAddress(&p, g_G);     Gp    = (float*)p;
        cudaGetSymbolAddress(&p, g_dummy); dummy = (float*)p;
        void* pA; cudaGetSymbolAddress(&pA, g_Ahf);
        void* pW; cudaGetSymbolAddress(&pW, g_Whf);

        void* fn = nullptr;
        cudaDriverEntryPointQueryResult qr;
        cudaGetDriverEntryPoint("cuTensorMapEncodeTiled", &fn, cudaEnableDefault, &qr);
        PFN_tmapEnc enc = (PFN_tmapEnc)fn;

        unsigned long long dimsA[2] = { (unsigned long long)H_, (unsigned long long)M_ };
        unsigned long long strA[1]  = { (unsigned long long)H_ * 2 };
        unsigned int boxA[2] = { (unsigned int)BK_, (unsigned int)BM_ };
        unsigned int es[2]   = { 1u, 1u };
        enc(&mapA, CU_TENSOR_MAP_DATA_TYPE_FLOAT16, 2, pA, dimsA, strA, boxA, es,
            CU_TENSOR_MAP_INTERLEAVE_NONE, CU_TENSOR_MAP_SWIZZLE_128B,
            CU_TENSOR_MAP_L2_PROMOTION_L2_128B, CU_TENSOR_MAP_FLOAT_OOB_FILL_NONE);
        unsigned long long dimsB[2] = { (unsigned long long)H_, (unsigned long long)V_ };
        unsigned int boxB[2] = { (unsigned int)BK_, (unsigned int)BN_ };
        enc(&mapB, CU_TENSOR_MAP_DATA_TYPE_FLOAT16, 2, pW, dimsB, strA, boxB, es,
            CU_TENSOR_MAP_INTERLEAVE_NONE, CU_TENSOR_MAP_SWIZZLE_128B,
            CU_TENSOR_MAP_L2_PROMOTION_L2_128B, CU_TENSOR_MAP_FLOAT_OOB_FILL_NONE);

        cudaFuncSetAttribute(gemm_f16, cudaFuncAttributeMaxDynamicSharedMemorySize, SMEM_TOTAL);
        inited = true;
    }

    // output layout: [logits (M_*V_), h_last (L,B,H), c_last (L,B,H)]
    const long long need = (long long)M_ * V_ + 2LL * L_ * B_ * H_;
    float *hl, *cl;
    if ((long long)out_size >= need) {
        hl = out + (size_t)M_ * V_;
        cl = hl + (size_t)L_ * B_ * H_;
    } else {
        hl = dummy;
        cl = dummy + (size_t)L_ * B_ * H_;
    }

    // 1. embedding + relu (fp16 A)
    embed_half_kernel<<<(M_ * H_ / 4) / 256, 256>>>(tgt, emb);

    // 2. two independent single-step LSTM layers
    for (int l = 0; l < L_; ++l) {
        hb_kernel<<<dim3(G4_ / 8, B_), dim3(32, 8)>>>(
            enc_h + (size_t)l * B_ * H_, W_hh + (size_t)l * G4_ * H_,
            b_ih + (size_t)l * G4_, b_hh + (size_t)l * G4_);
        wconv_kernel<<<((G4_ * H_ / 4) + 255) / 256, 256>>>(
            W_ih + (size_t)l * G4_ * H_, G4_ * H_ / 4);
        gemm_f16<<<dim3(M_ / BM_, G4_ / BN_), NTHR, SMEM_TOTAL>>>(
            mapA, mapB, Gp, G4_, nullptr);
        lstm_half_kernel<<<(M_ * H_) / 256, 256>>>(
            enc_c + (size_t)l * B_ * H_,
            hl + (size_t)l * B_ * H_, cl + (size_t)l * B_ * H_);
    }

    // 3. output projection: logits = X2 * W_out^T + b_out
    wconv_kernel<<<((V_ * H_ / 4) + 255) / 256, 256>>>(W_out, V_ * H_ / 4);
    gemm_f16<<<dim3(M_ / BM_, V_ / BN_), NTHR, SMEM_TOTAL>>>(
        mapA, mapB, out, V_, b_out);
}